// round 2
// baseline (speedup 1.0000x reference)
#include <cuda_runtime.h>
#include <math.h>

// Problem constants (fixed by the reference: B=16, N=1024, C=256)
#define B_ 16
#define N_ 1024
#define C_ 256

// ---------------------------------------------------------------------------
// Kernel 1: scores = (Q K^T + dis) / 16, masked -> -inf. Writes p_attn scratch.
// 128x128 output tile per block, 16x16 threads, 8x8 per thread, K-chunk 16.
// ---------------------------------------------------------------------------
__global__ __launch_bounds__(256) void qk_scores_kernel(
    const float* __restrict__ Q,
    const float* __restrict__ K,
    const float* __restrict__ dis,
    const int* __restrict__ mask,      // bool promoted to int32 by harness
    float* __restrict__ attn)
{
    __shared__ float Qs[16][132];   // [c][q], padded to dodge bank conflicts
    __shared__ float Ks[16][132];   // [c][k]

    const int b     = blockIdx.z;
    const int qBase = blockIdx.y * 128;
    const int kBase = blockIdx.x * 128;

    const float* Qb = Q + (size_t)b * N_ * C_;
    const float* Kb = K + (size_t)b * N_ * C_;

    const int tx  = threadIdx.x;     // 0..15
    const int ty  = threadIdx.y;     // 0..15
    const int tid = ty * 16 + tx;

    float acc[8][8];
#pragma unroll
    for (int i = 0; i < 8; i++)
#pragma unroll
        for (int j = 0; j < 8; j++) acc[i][j] = 0.0f;

    for (int c0 = 0; c0 < C_; c0 += 16) {
        // Load 128x16 tiles of Q and K (512 float4 each, 2 per thread)
#pragma unroll
        for (int e = 0; e < 2; e++) {
            int linear = tid + e * 256;
            int r  = linear >> 2;        // row within tile (0..127)
            int c4 = (linear & 3) * 4;   // starting c within chunk
            float4 vq = *reinterpret_cast<const float4*>(
                &Qb[(size_t)(qBase + r) * C_ + c0 + c4]);
            float4 vk = *reinterpret_cast<const float4*>(
                &Kb[(size_t)(kBase + r) * C_ + c0 + c4]);
            Qs[c4 + 0][r] = vq.x; Qs[c4 + 1][r] = vq.y;
            Qs[c4 + 2][r] = vq.z; Qs[c4 + 3][r] = vq.w;
            Ks[c4 + 0][r] = vk.x; Ks[c4 + 1][r] = vk.y;
            Ks[c4 + 2][r] = vk.z; Ks[c4 + 3][r] = vk.w;
        }
        __syncthreads();

#pragma unroll
        for (int cc = 0; cc < 16; cc++) {
            float rq[8], rk[8];
#pragma unroll
            for (int i = 0; i < 8; i++) rq[i] = Qs[cc][ty + i * 16];
#pragma unroll
            for (int j = 0; j < 8; j++) rk[j] = Ks[cc][tx + j * 16];
#pragma unroll
            for (int i = 0; i < 8; i++)
#pragma unroll
                for (int j = 0; j < 8; j++)
                    acc[i][j] = fmaf(rq[i], rk[j], acc[i][j]);
        }
        __syncthreads();
    }

    // Epilogue: add dis, scale by 1/sqrt(256)=0.0625, apply mask, store.
#pragma unroll
    for (int i = 0; i < 8; i++) {
        int q = qBase + ty + i * 16;
#pragma unroll
        for (int j = 0; j < 8; j++) {
            int k = kBase + tx + j * 16;
            size_t idx = ((size_t)b * N_ + q) * N_ + k;
            float s = (acc[i][j] + dis[idx]) * 0.0625f;
            attn[idx] = (mask[idx] != 0) ? -INFINITY : s;
        }
    }
}

// ---------------------------------------------------------------------------
// Kernel 2: in-place row softmax over the last dim (rows of length 1024).
// One block (256 threads) per row; 4 elements per thread.
// ---------------------------------------------------------------------------
__global__ __launch_bounds__(256) void softmax_kernel(float* __restrict__ attn)
{
    __shared__ float red[256];
    const size_t base = (size_t)blockIdx.x * N_;
    const int t = threadIdx.x;

    float v[4];
#pragma unroll
    for (int e = 0; e < 4; e++) v[e] = attn[base + t + e * 256];

    // max reduce
    float m = fmaxf(fmaxf(v[0], v[1]), fmaxf(v[2], v[3]));
    red[t] = m;
    __syncthreads();
#pragma unroll
    for (int s = 128; s >= 1; s >>= 1) {
        if (t < s) red[t] = fmaxf(red[t], red[t + s]);
        __syncthreads();
    }
    m = red[0];
    __syncthreads();

    // exp + sum reduce
    float p[4], lsum = 0.0f;
#pragma unroll
    for (int e = 0; e < 4; e++) {
        p[e] = __expf(v[e] - m);   // exp(-inf)=0 for masked entries
        lsum += p[e];
    }
    red[t] = lsum;
    __syncthreads();
#pragma unroll
    for (int s = 128; s >= 1; s >>= 1) {
        if (t < s) red[t] += red[t + s];
        __syncthreads();
    }
    float inv = 1.0f / red[0];

#pragma unroll
    for (int e = 0; e < 4; e++) attn[base + t + e * 256] = p[e] * inv;
}

// ---------------------------------------------------------------------------
// Kernel 3: p_val = p_attn @ V. Per batch: [1024 x 256] = [1024 x 1024][1024 x 256]
// 128x128 tile per block, 16x16 threads, 8x8 per thread, K-chunk 16.
// ---------------------------------------------------------------------------
__global__ __launch_bounds__(256) void pv_kernel(
    const float* __restrict__ P,
    const float* __restrict__ V,
    float* __restrict__ out)
{
    __shared__ float Ps[16][132];   // [k][q], padded
    __shared__ float Vs[16][128];   // [k][c], natural layout

    const int b     = blockIdx.z;
    const int qBase = blockIdx.y * 128;
    const int cBase = blockIdx.x * 128;

    const float* Pb = P + (size_t)b * N_ * N_;
    const float* Vb = V + (size_t)b * N_ * C_;

    const int tx  = threadIdx.x;
    const int ty  = threadIdx.y;
    const int tid = ty * 16 + tx;

    float acc[8][8];
#pragma unroll
    for (int i = 0; i < 8; i++)
#pragma unroll
        for (int j = 0; j < 8; j++) acc[i][j] = 0.0f;

    for (int k0 = 0; k0 < N_; k0 += 16) {
        // P tile: 128 q-rows x 16 k-cols  (512 float4, 2 per thread)
#pragma unroll
        for (int e = 0; e < 2; e++) {
            int linear = tid + e * 256;
            int q  = linear >> 2;
            int k4 = (linear & 3) * 4;
            float4 vp = *reinterpret_cast<const float4*>(
                &Pb[(size_t)(qBase + q) * N_ + k0 + k4]);
            Ps[k4 + 0][q] = vp.x; Ps[k4 + 1][q] = vp.y;
            Ps[k4 + 2][q] = vp.z; Ps[k4 + 3][q] = vp.w;
        }
        // V tile: 16 k-rows x 128 c-cols (512 float4, 2 per thread)
#pragma unroll
        for (int e = 0; e < 2; e++) {
            int linear = tid + e * 256;
            int k  = linear >> 5;          // 0..15
            int c4 = (linear & 31) * 4;    // 0..124
            float4 vv = *reinterpret_cast<const float4*>(
                &Vb[(size_t)(k0 + k) * C_ + cBase + c4]);
            Vs[k][c4 + 0] = vv.x; Vs[k][c4 + 1] = vv.y;
            Vs[k][c4 + 2] = vv.z; Vs[k][c4 + 3] = vv.w;
        }
        __syncthreads();

#pragma unroll
        for (int kk = 0; kk < 16; kk++) {
            float rp[8], rv[8];
#pragma unroll
            for (int i = 0; i < 8; i++) rp[i] = Ps[kk][ty + i * 16];
#pragma unroll
            for (int j = 0; j < 8; j++) rv[j] = Vs[kk][tx + j * 16];
#pragma unroll
            for (int i = 0; i < 8; i++)
#pragma unroll
                for (int j = 0; j < 8; j++)
                    acc[i][j] = fmaf(rp[i], rv[j], acc[i][j]);
        }
        __syncthreads();
    }

#pragma unroll
    for (int i = 0; i < 8; i++) {
        int q = qBase + ty + i * 16;
#pragma unroll
        for (int j = 0; j < 8; j++) {
            int c = cBase + tx + j * 16;
            out[((size_t)b * N_ + q) * C_ + c] = acc[i][j];
        }
    }
}

// ---------------------------------------------------------------------------
// Launch
// ---------------------------------------------------------------------------
extern "C" void kernel_launch(void* const* d_in, const int* in_sizes, int n_in,
                              void* d_out, int out_size)
{
    const float* Q    = (const float*)d_in[0];
    const float* K    = (const float*)d_in[1];
    const float* V    = (const float*)d_in[2];
    const int*   mask = (const int*)d_in[3];     // bool -> int32 (harness dtype set)
    const float* dis  = (const float*)d_in[4];

    float* out    = (float*)d_out;
    float* p_val  = out;                                   // [B, N, C]
    float* p_attn = out + (size_t)B_ * N_ * C_;            // [B, N, N]

    dim3 blk(16, 16);

    // 1) scores -> p_attn (with bias, scale, mask)
    qk_scores_kernel<<<dim3(N_ / 128, N_ / 128, B_), blk>>>(Q, K, dis, mask, p_attn);

    // 2) row softmax in place
    softmax_kernel<<<B_ * N_, 256>>>(p_attn);

    // 3) p_val = p_attn @ V
    pv_kernel<<<dim3(C_ / 128, N_ / 128, B_), blk>>>(p_attn, V, p_val);
}